// round 3
// baseline (speedup 1.0000x reference)
#include <cuda_runtime.h>
#include <cstdint>

#define B_ 256
#define T_ 1024
#define D_ 64
#define H_ 100
#define G_ 400   // 4*H
#define NBLK 128
#define L2E 1.44269504088896f

// Precomputed input-gate contributions, PERMUTED row order:
// xg[b][t][p] holds gate-row ((p&3)*H + (p>>2)).  ~419 MB.
__device__ float g_xg[(size_t)B_ * T_ * G_];
// Per-block mirror of h for k-pairs 50..99 (m = 25..49): float4 = {h0_2k, h0_2k1, h1_2k, h1_2k1}
__device__ float4 g_hg[NBLK][25];

// ---------------------------------------------------------------------------
// Packed f32x2 helpers
// ---------------------------------------------------------------------------
__device__ __forceinline__ unsigned long long ffma2(unsigned long long a,
                                                    unsigned long long b,
                                                    unsigned long long c) {
    unsigned long long d;
    asm("fma.rn.f32x2 %0, %1, %2, %3;" : "=l"(d) : "l"(a), "l"(b), "l"(c));
    return d;
}
__device__ __forceinline__ unsigned long long add2(unsigned long long a,
                                                   unsigned long long b) {
    unsigned long long d;
    asm("add.rn.f32x2 %0, %1, %2;" : "=l"(d) : "l"(a), "l"(b));
    return d;
}
__device__ __forceinline__ unsigned long long pack2(float x, float y) {
    return ((unsigned long long)__float_as_uint(y) << 32) |
           (unsigned long long)__float_as_uint(x);
}
__device__ __forceinline__ unsigned long long pk2(float2 v) { return pack2(v.x, v.y); }
__device__ __forceinline__ float lo2(unsigned long long v) {
    return __uint_as_float((unsigned)v);
}
__device__ __forceinline__ float hi2(unsigned long long v) {
    return __uint_as_float((unsigned)(v >> 32));
}
__device__ __forceinline__ float ex2a(float x) {
    float r; asm("ex2.approx.ftz.f32 %0, %1;" : "=f"(r) : "f"(x)); return r;
}
__device__ __forceinline__ float rcpa(float x) {
    float r; asm("rcp.approx.ftz.f32 %0, %1;" : "=f"(r) : "f"(x)); return r;
}
// sigmoid(x) = 1 - 1/(e^x+1)  (lm=log2e, s=1);  tanh(x) = 1 - 2/(e^2x+1)  (lm=2log2e, s=2)
__device__ __forceinline__ float uact(float x, float lm, float s) {
    return 1.0f - s * rcpa(ex2a(lm * x) + 1.0f);
}

// ---------------------------------------------------------------------------
// Kernel 1: xg[b,t,p] = x[b,t,:] . W_ih[row,:] + (b_ih+b_hh)[row],
//           row = (p&3)*H + (p>>2)  (quad-permuted for the lstm kernel).
// ---------------------------------------------------------------------------
__global__ __launch_bounds__(512, 1)
void xg_kernel(const float* __restrict__ x,
               const float* __restrict__ W_ih,
               const float* __restrict__ b_ih,
               const float* __restrict__ b_hh) {
    __shared__ ulonglong2 xs[64][16];   // 64 t x 64 k fp32 tile (16 KB)

    const int b   = blockIdx.y;
    const int t0  = blockIdx.x * 64;
    const int tid = threadIdx.x;

    {   // coalesced float4 tile load
        const float4* src = (const float4*)(x + ((size_t)b * T_ + t0) * D_);
        float4* dst = (float4*)xs;
        for (int i = tid; i < 64 * 16; i += 512) dst[i] = src[i];
    }

    unsigned long long w2[32];
    float bias = 0.0f;
    if (tid < G_) {
        const int row = (tid & 3) * H_ + (tid >> 2);
        const float4* wrow = (const float4*)(W_ih + (size_t)row * D_);
#pragma unroll
        for (int i = 0; i < 16; i++) {
            float4 v = wrow[i];
            w2[2 * i]     = pack2(v.x, v.y);
            w2[2 * i + 1] = pack2(v.z, v.w);
        }
        bias = b_ih[row] + b_hh[row];
    }
    __syncthreads();

    if (tid < G_) {
        float* out = g_xg + ((size_t)b * T_ + t0) * G_ + tid;
#pragma unroll 2
        for (int t = 0; t < 64; t++) {
            unsigned long long a0 = 0ull, a1 = 0ull;
#pragma unroll
            for (int i = 0; i < 16; i++) {
                ulonglong2 xv = xs[t][i];          // broadcast LDS.128
                a0 = ffma2(w2[2 * i],     xv.x, a0);
                a1 = ffma2(w2[2 * i + 1], xv.y, a1);
            }
            unsigned long long s2 = add2(a0, a1);
            out[(size_t)t * G_] = lo2(s2) + hi2(s2) + bias;
        }
    }
}

// ---------------------------------------------------------------------------
// Kernel 2: recurrence. 128 blocks x 2 batch rows, 416 threads.
// Thread p<400: gate = p&3, unit j = p>>2, owns W_hh row (gate*H+j) packed
// as 50 f32x2 regs. h operand split across two pipes:
//   m=0..24  -> shared  hsm[m]      (LDS.128)
//   m=25..49 -> global  g_hg[blk]   (LDG.128, L1-resident, same SM)
// Each float4 m = {h0[2m],h0[2m+1],h1[2m],h1[2m+1]}: one weight reg feeds both
// batch chains. Gates stored quad-permuted -> phase B is one LDS.128.
// ---------------------------------------------------------------------------
__global__ __launch_bounds__(416, 1)
void lstm_kernel(const float* __restrict__ h0,
                 const float* __restrict__ c0,
                 const float* __restrict__ W_hh,
                 const float* __restrict__ W_fc,
                 const float* __restrict__ b_fc,
                 float* __restrict__ out) {
    __shared__ float4 hsm[25];         // h k-pairs 0..24
    __shared__ float gbuf[2][G_];      // activated gates, layout [b][j*4+gate]
    __shared__ float wfc_s[H_];

    const int tid    = threadIdx.x;
    const int blk    = blockIdx.x;
    const int batch0 = blk * 2;
    const int gate   = tid & 3;
    const int j      = tid >> 2;

    // --- init h (both halves), wfc ---
    if (tid < H_) {
        float a0 = h0[(size_t)(batch0)     * H_ + tid];
        float a1 = h0[(size_t)(batch0 + 1) * H_ + tid];
        int m = tid >> 1, comp = tid & 1;
        float* base = (m < 25) ? (float*)&hsm[m] : (float*)&g_hg[blk][m - 25];
        base[comp]     = a0;
        base[2 + comp] = a1;
        wfc_s[tid] = W_fc[tid];
    }

    // --- phase-B persistent state: thread tid<200 owns (b = tid/100, jj) ---
    float cr = 0.0f;
    int pb_b = 0, pb_j = 0;
    if (tid < 2 * H_) {
        pb_b = (tid >= H_);
        pb_j = tid - pb_b * H_;
        cr = c0[(size_t)(batch0 + pb_b) * H_ + pb_j];
    }

    // --- weights + per-gate activation constants ---
    unsigned long long w2[50];
    float lm = L2E, sc = 1.0f;
    const float* xp0 = g_xg + (size_t)(batch0)     * T_ * G_ + tid;
    const float* xp1 = g_xg + (size_t)(batch0 + 1) * T_ * G_ + tid;
    float xgc0 = 0.0f, xgc1 = 0.0f;
    if (tid < G_) {
        const int row = gate * H_ + j;
        const float4* wrow = (const float4*)(W_hh + (size_t)row * H_);
#pragma unroll
        for (int i = 0; i < 25; i++) {
            float4 v = wrow[i];
            w2[2 * i]     = pack2(v.x, v.y);
            w2[2 * i + 1] = pack2(v.z, v.w);
        }
        if (gate == 2) { lm = 2.0f * L2E; sc = 2.0f; }
        xgc0 = xp0[0];
        xgc1 = xp1[0];
    }
    __syncthreads();

    const float4* hg = g_hg[blk];

    for (int t = 0; t < T_; t++) {
        // prefetch next step's xg (hidden behind the matvec)
        float xgn0 = 0.0f, xgn1 = 0.0f;
        if (tid < G_ && t + 1 < T_) {
            xgn0 = xp0[(size_t)(t + 1) * G_];
            xgn1 = xp1[(size_t)(t + 1) * G_];
        }

        if (tid < G_) {
            unsigned long long a0 = 0, a1 = 0, b0 = 0, b1 = 0;
#pragma unroll
            for (int m = 0; m < 25; m += 2) {       // shared half (LDS pipe)
                float4 hv = hsm[m];
                a0 = ffma2(w2[m], pk2(make_float2(hv.x, hv.y)), a0);
                b0 = ffma2(w2[m], pk2(make_float2(hv.z, hv.w)), b0);
                if (m + 1 < 25) {
                    float4 hw = hsm[m + 1];
                    a1 = ffma2(w2[m + 1], pk2(make_float2(hw.x, hw.y)), a1);
                    b1 = ffma2(w2[m + 1], pk2(make_float2(hw.z, hw.w)), b1);
                }
            }
#pragma unroll
            for (int m = 0; m < 25; m += 2) {       // global half (LDG/L1 pipe)
                float4 hv = __ldg(&hg[m]);
                a0 = ffma2(w2[25 + m], pk2(make_float2(hv.x, hv.y)), a0);
                b0 = ffma2(w2[25 + m], pk2(make_float2(hv.z, hv.w)), b0);
                if (m + 1 < 25) {
                    float4 hw = __ldg(&hg[m + 1]);
                    a1 = ffma2(w2[26 + m], pk2(make_float2(hw.x, hw.y)), a1);
                    b1 = ffma2(w2[26 + m], pk2(make_float2(hw.z, hw.w)), b1);
                }
            }
            unsigned long long s0 = add2(a0, a1);
            unsigned long long s1 = add2(b0, b1);
            float acc0 = lo2(s0) + hi2(s0) + xgc0;
            float acc1 = lo2(s1) + hi2(s1) + xgc1;

            gbuf[0][tid] = uact(acc0, lm, sc);     // branch-free activation
            gbuf[1][tid] = uact(acc1, lm, sc);
            xgc0 = xgn0;
            xgc1 = xgn1;
        }
        __syncthreads();

        // phase B: 200 threads, one LDS.128 each
        if (tid < 2 * H_) {
            float4 g4 = *(const float4*)&gbuf[pb_b][pb_j * 4];  // {i,f,g,o}
            cr = g4.y * cr + g4.x * g4.z;
            float hv = g4.w * uact(cr, 2.0f * L2E, 2.0f);
            int m = pb_j >> 1, comp = 2 * pb_b + (pb_j & 1);
            if (m < 25) ((float*)&hsm[m])[comp] = hv;
            else        ((float*)&g_hg[blk][m - 25])[comp] = hv;
        }
        __syncthreads();
    }

    // FC head: out[b] = h_T . W_fc + b_fc
    if (tid < 2) {
        float acc = b_fc[0];
#pragma unroll 4
        for (int jj = 0; jj < H_; jj++) {
            int m = jj >> 1, comp = 2 * tid + (jj & 1);
            float hv = (m < 25) ? ((const float*)&hsm[m])[comp]
                                : ((const float*)&g_hg[blk][m - 25])[comp];
            acc += hv * wfc_s[jj];
        }
        out[batch0 + tid] = acc;
    }
}

// ---------------------------------------------------------------------------
extern "C" void kernel_launch(void* const* d_in, const int* in_sizes, int n_in,
                              void* d_out, int out_size) {
    const float* x    = (const float*)d_in[0];
    const float* h0   = (const float*)d_in[1];
    const float* c0   = (const float*)d_in[2];
    const float* W_ih = (const float*)d_in[3];
    const float* W_hh = (const float*)d_in[4];
    const float* b_ih = (const float*)d_in[5];
    const float* b_hh = (const float*)d_in[6];
    const float* W_fc = (const float*)d_in[7];
    const float* b_fc = (const float*)d_in[8];
    float* out = (float*)d_out;

    dim3 grid1(T_ / 64, B_);
    xg_kernel<<<grid1, 512>>>(x, W_ih, b_ih, b_hh);

    lstm_kernel<<<NBLK, 416>>>(h0, c0, W_hh, W_fc, b_fc, out);
}

// round 4
// speedup vs baseline: 2.0140x; 2.0140x over previous
#include <cuda_runtime.h>
#include <cstdint>

#define B_ 256
#define T_ 1024
#define D_ 64
#define H_ 100
#define G_ 400   // 4*H
#define NBLK 128
#define L2E 1.44269504088896f

// Precomputed input-gate contributions, PERMUTED row order:
// xg[b][t][p] holds gate-row ((p&3)*H + (p>>2)).  ~419 MB.
__device__ float g_xg[(size_t)B_ * T_ * G_];

// ---------------------------------------------------------------------------
// Packed f32x2 helpers
// ---------------------------------------------------------------------------
__device__ __forceinline__ unsigned long long ffma2(unsigned long long a,
                                                    unsigned long long b,
                                                    unsigned long long c) {
    unsigned long long d;
    asm("fma.rn.f32x2 %0, %1, %2, %3;" : "=l"(d) : "l"(a), "l"(b), "l"(c));
    return d;
}
__device__ __forceinline__ unsigned long long add2(unsigned long long a,
                                                   unsigned long long b) {
    unsigned long long d;
    asm("add.rn.f32x2 %0, %1, %2;" : "=l"(d) : "l"(a), "l"(b));
    return d;
}
__device__ __forceinline__ unsigned long long pack2(float x, float y) {
    return ((unsigned long long)__float_as_uint(y) << 32) |
           (unsigned long long)__float_as_uint(x);
}
__device__ __forceinline__ float lo2(unsigned long long v) {
    return __uint_as_float((unsigned)v);
}
__device__ __forceinline__ float hi2(unsigned long long v) {
    return __uint_as_float((unsigned)(v >> 32));
}
__device__ __forceinline__ float ex2a(float x) {
    float r; asm("ex2.approx.ftz.f32 %0, %1;" : "=f"(r) : "f"(x)); return r;
}
__device__ __forceinline__ float rcpa(float x) {
    float r; asm("rcp.approx.ftz.f32 %0, %1;" : "=f"(r) : "f"(x)); return r;
}
// sigmoid(x) = 1 - 1/(e^x+1)  (lm=log2e, s=1);  tanh(x) = 1 - 2/(e^2x+1)
__device__ __forceinline__ float uact(float x, float lm, float s) {
    return 1.0f - s * rcpa(ex2a(lm * x) + 1.0f);
}

// ---------------------------------------------------------------------------
// Kernel 1: xg[b,t,p] = x[b,t,:] . W_ih[row,:] + (b_ih+b_hh)[row],
//           row = (p&3)*H + (p>>2)  (quad-permuted for the lstm kernel).
// (R1 structure — fastest measured variant.)
// ---------------------------------------------------------------------------
__global__ __launch_bounds__(512, 1)
void xg_kernel(const float* __restrict__ x,
               const float* __restrict__ W_ih,
               const float* __restrict__ b_ih,
               const float* __restrict__ b_hh) {
    __shared__ ulonglong2 xs[64][16];   // 64 t x 64 k fp32 tile (16 KB)

    const int b   = blockIdx.y;
    const int t0  = blockIdx.x * 64;
    const int tid = threadIdx.x;

    {   // coalesced float4 tile load
        const float4* src = (const float4*)(x + ((size_t)b * T_ + t0) * D_);
        float4* dst = (float4*)xs;
        for (int i = tid; i < 64 * 16; i += 512) dst[i] = src[i];
    }

    unsigned long long w2[32];
    float bias = 0.0f;
    if (tid < G_) {
        const int row = (tid & 3) * H_ + (tid >> 2);
        const float4* wrow = (const float4*)(W_ih + (size_t)row * D_);
#pragma unroll
        for (int i = 0; i < 16; i++) {
            float4 v = wrow[i];
            w2[2 * i]     = pack2(v.x, v.y);
            w2[2 * i + 1] = pack2(v.z, v.w);
        }
        bias = b_ih[row] + b_hh[row];
    }
    __syncthreads();

    if (tid < G_) {
        float* out = g_xg + ((size_t)b * T_ + t0) * G_ + tid;
#pragma unroll 2
        for (int t = 0; t < 64; t++) {
            unsigned long long a0 = 0ull, a1 = 0ull;
#pragma unroll
            for (int i = 0; i < 16; i++) {
                ulonglong2 xv = xs[t][i];          // broadcast LDS.128
                a0 = ffma2(w2[2 * i],     xv.x, a0);
                a1 = ffma2(w2[2 * i + 1], xv.y, a1);
            }
            unsigned long long s2 = add2(a0, a1);
            out[(size_t)t * G_] = lo2(s2) + hi2(s2) + bias;
        }
    }
}

// ---------------------------------------------------------------------------
// Kernel 2: recurrence, split-k. 128 blocks x 2 batch rows, 800 threads.
// Thread: r = tid>>1 (permuted gate-row, gate=r&3, j=r>>2), s = tid&1
// (k-half). Holds 25 packed W_hh k-pairs (50 regs) -> 25 warps/SM.
// h in shared, batch-interleaved float4: hs4[i]={h0[2i],h0[2i+1],h1[2i],h1[2i+1]}
// -> one LDS.128 + one weight reg feed BOTH batch chains.
// Partner lanes (tid^1, same warp) swap k-half partials with 2 shfl.xor.
// Thread finalizes batch s: activation + STS gbuf. Phase B as R1 (all-shared).
// ---------------------------------------------------------------------------
__global__ __launch_bounds__(800, 1)
void lstm_kernel(const float* __restrict__ h0,
                 const float* __restrict__ c0,
                 const float* __restrict__ W_hh,
                 const float* __restrict__ W_fc,
                 const float* __restrict__ b_fc,
                 float* __restrict__ out) {
    __shared__ float4 hs4[50];         // k-pair i, both batches interleaved
    __shared__ float gbuf[2][G_];      // [batch][r], quad-permuted rows
    __shared__ float wfc_s[H_];

    const int tid    = threadIdx.x;
    const int batch0 = blockIdx.x * 2;
    const int r      = tid >> 1;
    const int s      = tid & 1;
    const int gate   = r & 3;
    const int j      = r >> 2;

    // --- init h, wfc ---
    if (tid < H_) {
        int i = tid >> 1, comp = tid & 1;
        ((float*)&hs4[i])[comp]     = h0[(size_t)(batch0)     * H_ + tid];
        ((float*)&hs4[i])[2 + comp] = h0[(size_t)(batch0 + 1) * H_ + tid];
        wfc_s[tid] = W_fc[tid];
    }

    // --- phase-B persistent state: tid<200 owns (pb_b, pb_j) ---
    float cr = 0.0f;
    int pb_b = 0, pb_j = 0;
    if (tid < 2 * H_) {
        pb_b = (tid >= H_);
        pb_j = tid - pb_b * H_;
        cr = c0[(size_t)(batch0 + pb_b) * H_ + pb_j];
    }

    // --- weights: k-pairs [s*25, s*25+25) of W_hh row (gate*H + j) ---
    unsigned long long w2[25];
    {
        const float2* wrow =
            (const float2*)(W_hh + (size_t)(gate * H_ + j) * H_) + s * 25;
#pragma unroll
        for (int i = 0; i < 25; i++) {
            float2 v = wrow[i];
            w2[i] = pack2(v.x, v.y);
        }
    }
    float lm = (gate == 2) ? 2.0f * L2E : L2E;
    float sc = (gate == 2) ? 2.0f : 1.0f;

    // xg stream for MY batch (batch0+s), permuted row r
    const float* xp = g_xg + (size_t)(batch0 + s) * T_ * G_ + r;
    float xgc = xp[0];

    __syncthreads();

    const float4* hbase = hs4 + s * 25;

    for (int t = 0; t < T_; t++) {
        float xgn = (t + 1 < T_) ? xp[(size_t)(t + 1) * G_] : 0.0f;  // prefetch

        // matvec over my k-half, both batches from one load + one weight reg
        unsigned long long a0 = 0ull, b0 = 0ull;
#pragma unroll
        for (int i = 0; i < 25; i++) {
            float4 hv = hbase[i];                  // LDS.128, dual broadcast
            a0 = ffma2(w2[i], pack2(hv.x, hv.y), a0);
            b0 = ffma2(w2[i], pack2(hv.z, hv.w), b0);
        }
        float p0 = lo2(a0) + hi2(a0);              // batch0 partial (my half)
        float p1 = lo2(b0) + hi2(b0);              // batch1 partial

        // combine with partner (other k-half): 2 shuffles, off the FMA chain
        float q0 = __shfl_xor_sync(0xffffffffu, p0, 1);
        float q1 = __shfl_xor_sync(0xffffffffu, p1, 1);
        float full = (s ? (p1 + q1) : (p0 + q0)) + xgc;

        gbuf[s][r] = uact(full, lm, sc);           // branch-free activation
        xgc = xgn;
        __syncthreads();

        // phase B: 200 threads, one LDS.128 each
        if (tid < 2 * H_) {
            float4 g4 = *(const float4*)&gbuf[pb_b][pb_j * 4];  // {i,f,g,o}
            cr = g4.y * cr + g4.x * g4.z;
            float hv = g4.w * uact(cr, 2.0f * L2E, 2.0f);
            ((float*)&hs4[pb_j >> 1])[(pb_j & 1) + 2 * pb_b] = hv;
        }
        __syncthreads();
    }

    // FC head: out[b] = h_T . W_fc + b_fc
    if (tid < 2) {
        float acc = b_fc[0];
#pragma unroll 4
        for (int jj = 0; jj < H_; jj++) {
            float hv = ((const float*)&hs4[jj >> 1])[(jj & 1) + 2 * tid];
            acc += hv * wfc_s[jj];
        }
        out[batch0 + tid] = acc;
    }
}

// ---------------------------------------------------------------------------
extern "C" void kernel_launch(void* const* d_in, const int* in_sizes, int n_in,
                              void* d_out, int out_size) {
    const float* x    = (const float*)d_in[0];
    const float* h0   = (const float*)d_in[1];
    const float* c0   = (const float*)d_in[2];
    const float* W_ih = (const float*)d_in[3];
    const float* W_hh = (const float*)d_in[4];
    const float* b_ih = (const float*)d_in[5];
    const float* b_hh = (const float*)d_in[6];
    const float* W_fc = (const float*)d_in[7];
    const float* b_fc = (const float*)d_in[8];
    float* out = (float*)d_out;

    dim3 grid1(T_ / 64, B_);
    xg_kernel<<<grid1, 512>>>(x, W_ih, b_ih, b_hh);

    lstm_kernel<<<NBLK, 800>>>(h0, c0, W_hh, W_fc, b_fc, out);
}

// round 5
// speedup vs baseline: 2.0308x; 1.0083x over previous
#include <cuda_runtime.h>
#include <cstdint>

#define B_ 256
#define T_ 1024
#define D_ 64
#define H_ 100
#define G_ 400   // 4*H
#define NBLK 128
#define L2E 1.44269504088896f

// Precomputed input-gate contributions, PERMUTED row order:
// xg[b][t][p] holds gate-row ((p&3)*H + (p>>2)).  ~419 MB.
__device__ float g_xg[(size_t)B_ * T_ * G_];

// ---------------------------------------------------------------------------
// Packed f32x2 helpers
// ---------------------------------------------------------------------------
__device__ __forceinline__ unsigned long long ffma2(unsigned long long a,
                                                    unsigned long long b,
                                                    unsigned long long c) {
    unsigned long long d;
    asm("fma.rn.f32x2 %0, %1, %2, %3;" : "=l"(d) : "l"(a), "l"(b), "l"(c));
    return d;
}
__device__ __forceinline__ unsigned long long add2(unsigned long long a,
                                                   unsigned long long b) {
    unsigned long long d;
    asm("add.rn.f32x2 %0, %1, %2;" : "=l"(d) : "l"(a), "l"(b));
    return d;
}
__device__ __forceinline__ unsigned long long pack2(float x, float y) {
    return ((unsigned long long)__float_as_uint(y) << 32) |
           (unsigned long long)__float_as_uint(x);
}
__device__ __forceinline__ float lo2(unsigned long long v) {
    return __uint_as_float((unsigned)v);
}
__device__ __forceinline__ float hi2(unsigned long long v) {
    return __uint_as_float((unsigned)(v >> 32));
}
__device__ __forceinline__ float ex2a(float x) {
    float r; asm("ex2.approx.ftz.f32 %0, %1;" : "=f"(r) : "f"(x)); return r;
}
__device__ __forceinline__ float rcpa(float x) {
    float r; asm("rcp.approx.ftz.f32 %0, %1;" : "=f"(r) : "f"(x)); return r;
}
// sigmoid(x) = 1 - 1/(e^x+1)  (lm=log2e, s=1);  tanh(x) = 1 - 2/(e^2x+1)
__device__ __forceinline__ float uact(float x, float lm, float s) {
    return 1.0f - s * rcpa(ex2a(lm * x) + 1.0f);
}

// ---------------------------------------------------------------------------
// Kernel 1: xg[b,t,p] = x[b,t,:] . W_ih[row,:] + (b_ih+b_hh)[row],
//           row = (p&3)*H + (p>>2)  (quad-permuted for the lstm kernel).
// 2-timestep inner interleave -> 4 independent FFMA2 chains.
// ---------------------------------------------------------------------------
__global__ __launch_bounds__(512, 1)
void xg_kernel(const float* __restrict__ x,
               const float* __restrict__ W_ih,
               const float* __restrict__ b_ih,
               const float* __restrict__ b_hh) {
    __shared__ ulonglong2 xs[64][16];   // 64 t x 64 k fp32 tile (16 KB)

    const int b   = blockIdx.y;
    const int t0  = blockIdx.x * 64;
    const int tid = threadIdx.x;

    {   // coalesced float4 tile load
        const float4* src = (const float4*)(x + ((size_t)b * T_ + t0) * D_);
        float4* dst = (float4*)xs;
        for (int i = tid; i < 64 * 16; i += 512) dst[i] = src[i];
    }

    unsigned long long w2[32];
    float bias = 0.0f;
    if (tid < G_) {
        const int row = (tid & 3) * H_ + (tid >> 2);
        const float4* wrow = (const float4*)(W_ih + (size_t)row * D_);
#pragma unroll
        for (int i = 0; i < 16; i++) {
            float4 v = wrow[i];
            w2[2 * i]     = pack2(v.x, v.y);
            w2[2 * i + 1] = pack2(v.z, v.w);
        }
        bias = b_ih[row] + b_hh[row];
    }
    __syncthreads();

    if (tid < G_) {
        float* out = g_xg + ((size_t)b * T_ + t0) * G_ + tid;
        for (int t = 0; t < 64; t += 2) {
            unsigned long long a0 = 0ull, a1 = 0ull, a2 = 0ull, a3 = 0ull;
#pragma unroll
            for (int i = 0; i < 16; i++) {
                ulonglong2 xv = xs[t][i];          // broadcast LDS.128
                ulonglong2 xw = xs[t + 1][i];
                a0 = ffma2(w2[2 * i],     xv.x, a0);
                a1 = ffma2(w2[2 * i + 1], xv.y, a1);
                a2 = ffma2(w2[2 * i],     xw.x, a2);
                a3 = ffma2(w2[2 * i + 1], xw.y, a3);
            }
            unsigned long long s0 = add2(a0, a1);
            unsigned long long s1 = add2(a2, a3);
            out[(size_t)t * G_]       = lo2(s0) + hi2(s0) + bias;
            out[(size_t)(t + 1) * G_] = lo2(s1) + hi2(s1) + bias;
        }
    }
}

// ---------------------------------------------------------------------------
// Kernel 2: recurrence, split-k, ONE barrier per step.
// 128 blocks x 2 batch rows, 800 threads. Thread: r = tid>>1 (permuted row,
// gate=r&3, j=r>>2), s = tid&1 (k-half AND final batch owner).
// Matvec: 25 LDS.128 (dual-batch float4) + 50 FFMA2 per thread;
// k-half combine = 1 shfl_xor. Gate exchange: all 4 gates of unit j live in
// this warp (even shfl deltas preserve batch parity) -> 3 shfl_down deliver
// {f,g,o} to the gate-0 lane, which owns c and writes h into the OTHER hs4
// buffer. One __syncthreads per step.
// ---------------------------------------------------------------------------
__global__ __launch_bounds__(800, 1)
void lstm_kernel(const float* __restrict__ h0,
                 const float* __restrict__ c0,
                 const float* __restrict__ W_hh,
                 const float* __restrict__ W_fc,
                 const float* __restrict__ b_fc,
                 float* __restrict__ out) {
    __shared__ float4 hs4[2][50];      // [buf][k-pair i] = {h0_2i,h0_2i+1,h1_2i,h1_2i+1}
    __shared__ float wfc_s[H_];

    const int tid    = threadIdx.x;
    const int batch0 = blockIdx.x * 2;
    const int r      = tid >> 1;       // permuted gate-row
    const int s      = tid & 1;        // k-half + batch owner
    const int gate   = r & 3;
    const int j      = r >> 2;

    // --- init h buffer 0, wfc ---
    if (tid < H_) {
        int i = tid >> 1, comp = tid & 1;
        ((float*)&hs4[0][i])[comp]     = h0[(size_t)(batch0)     * H_ + tid];
        ((float*)&hs4[0][i])[2 + comp] = h0[(size_t)(batch0 + 1) * H_ + tid];
        wfc_s[tid] = W_fc[tid];
    }

    // --- weights: k-pairs [s*25, s*25+25) of W_hh row (gate*H + j) ---
    unsigned long long w2[25];
    {
        const float2* wrow =
            (const float2*)(W_hh + (size_t)(gate * H_ + j) * H_) + s * 25;
#pragma unroll
        for (int i = 0; i < 25; i++) {
            float2 v = wrow[i];
            w2[i] = pack2(v.x, v.y);
        }
    }
    float lm = (gate == 2) ? 2.0f * L2E : L2E;
    float sc = (gate == 2) ? 2.0f : 1.0f;

    // c owned by gate-0 threads: (unit j, batch s)
    float cr = (gate == 0) ? c0[(size_t)(batch0 + s) * H_ + j] : 0.0f;

    // xg stream for my batch (batch0+s), permuted row r
    const float* xp = g_xg + (size_t)(batch0 + s) * T_ * G_ + r;
    float xgc = xp[0];

    __syncthreads();

    int cur = 0;
    for (int t = 0; t < T_; t++) {
        float xgn = (t + 1 < T_) ? xp[(size_t)(t + 1) * G_] : 0.0f;  // prefetch

        // matvec over my k-half, both batches from one load + one weight reg
        const float4* hbase = hs4[cur] + s * 25;
        unsigned long long a0 = 0ull, b0 = 0ull;
#pragma unroll
        for (int i = 0; i < 25; i++) {
            float4 hv = hbase[i];                  // LDS.128
            a0 = ffma2(w2[i], pack2(hv.x, hv.y), a0);
            b0 = ffma2(w2[i], pack2(hv.z, hv.w), b0);
        }
        float p0 = lo2(a0) + hi2(a0);              // batch0 partial (my half)
        float p1 = lo2(b0) + hi2(b0);              // batch1 partial

        // combine k-halves with partner lane (tid^1)
        float q0 = __shfl_xor_sync(0xffffffffu, p0, 1);
        float q1 = __shfl_xor_sync(0xffffffffu, p1, 1);
        float full = (s ? (p1 + q1) : (p0 + q0)) + xgc;

        float gv = uact(full, lm, sc);             // my gate, my batch

        // gather {f,g,o} to the gate-0 lane (even deltas keep batch parity)
        float fv = __shfl_down_sync(0xffffffffu, gv, 2);
        float gg = __shfl_down_sync(0xffffffffu, gv, 4);
        float ov = __shfl_down_sync(0xffffffffu, gv, 6);

        if (gate == 0) {                           // owns c for (j, batch s)
            cr = fv * cr + gv * gg;
            float hv = ov * uact(cr, 2.0f * L2E, 2.0f);
            ((float*)&hs4[cur ^ 1][j >> 1])[(j & 1) + 2 * s] = hv;
        }
        xgc = xgn;
        __syncthreads();
        cur ^= 1;
    }

    // FC head: out[b] = h_T . W_fc + b_fc   (h_T is in hs4[cur])
    if (tid < 2) {
        float acc = b_fc[0];
#pragma unroll 4
        for (int jj = 0; jj < H_; jj++) {
            float hv = ((const float*)&hs4[cur][jj >> 1])[(jj & 1) + 2 * tid];
            acc += hv * wfc_s[jj];
        }
        out[batch0 + tid] = acc;
    }
}

// ---------------------------------------------------------------------------
extern "C" void kernel_launch(void* const* d_in, const int* in_sizes, int n_in,
                              void* d_out, int out_size) {
    const float* x    = (const float*)d_in[0];
    const float* h0   = (const float*)d_in[1];
    const float* c0   = (const float*)d_in[2];
    const float* W_ih = (const float*)d_in[3];
    const float* W_hh = (const float*)d_in[4];
    const float* b_ih = (const float*)d_in[5];
    const float* b_hh = (const float*)d_in[6];
    const float* W_fc = (const float*)d_in[7];
    const float* b_fc = (const float*)d_in[8];
    float* out = (float*)d_out;

    dim3 grid1(T_ / 64, B_);
    xg_kernel<<<grid1, 512>>>(x, W_ih, b_ih, b_hh);

    lstm_kernel<<<NBLK, 800>>>(h0, c0, W_hh, W_fc, b_fc, out);
}